// round 13
// baseline (speedup 1.0000x reference)
#include <cuda_runtime.h>
#include <cuda_bf16.h>
#include <cstdint>

// DenseGridNet via warp-level mma.sync bf16 (m16n8k16), split-bf16 x3.
// R13: warp-autonomous tiles. Each warp owns 16 points: cp.async gathers into
// a warp-private smem slice (prefetched one warp-tile ahead), splitpack into a
// warp-private A0 slice, __syncwarp only -- no __syncthreads in the main loop.

#define THREADS 256
#define NCTA 444
#define AS 24    // A0 slice row stride (words) -> conflict-free frag loads
#define GQ 13    // staged quads per point -> optimal LDS.128 phases

struct __align__(16) Smem {
    uint4 B1[8 * 32];          // layer1 fused hi/lo B frags (bias row folded)
    uint4 B2[32 * 32];         // layer2
    uint4 B3[4 * 32];          // layer3
    float b2s[64], b3s[8];
    uint32_t A0h[8][8 * AS];   // per-warp pre-split input frags [kpair][pt]
    uint32_t A0l[8][8 * AS];
    float4 G[8][16 * GQ];      // per-warp staged texels, 12 used + 1 pad / pt
};
#define SMEM_BYTES ((int)sizeof(Smem))

__device__ __forceinline__ uint32_t smaddr(const void* p) {
    uint32_t a;
    asm("{ .reg .u64 t; cvta.to.shared.u64 t, %1; cvt.u32.u64 %0, t; }"
        : "=r"(a) : "l"(p));
    return a;
}
#define CPA16(sm, gm) \
    asm volatile("cp.async.ca.shared.global [%0], [%1], 16;" \
                 :: "r"(sm), "l"(gm) : "memory")
#define CPA_COMMIT()   asm volatile("cp.async.commit_group;" ::: "memory")
#define CPA_WAIT_ALL() asm volatile("cp.async.wait_group 0;" ::: "memory")

__device__ __forceinline__ void splitpack(float v0, float v1,
                                          uint32_t& hi, uint32_t& lo) {
    asm("cvt.rn.bf16x2.f32 %0, %1, %2;" : "=r"(hi) : "f"(v1), "f"(v0));
    float r0 = __uint_as_float(hi << 16);
    float r1 = __uint_as_float(hi & 0xFFFF0000u);
    asm("cvt.rn.bf16x2.f32 %0, %1, %2;" : "=r"(lo) : "f"(v1 - r1), "f"(v0 - r0));
}
__device__ __forceinline__ void splitval(float v, uint32_t pos16,
                                         uint32_t& hi, uint32_t& lo) {
    __nv_bfloat16 h = __float2bfloat16(v);
    float r = v - __bfloat162float(h);
    __nv_bfloat16 l = __float2bfloat16(r);
    uint16_t hb, lb;
    __builtin_memcpy(&hb, &h, 2);
    __builtin_memcpy(&lb, &l, 2);
    hi |= (uint32_t)hb << pos16;
    lo |= (uint32_t)lb << pos16;
}

__device__ __forceinline__ void mma16816(float c[4], const uint32_t a[4],
                                         uint32_t b0, uint32_t b1) {
    asm volatile(
        "mma.sync.aligned.m16n8k16.row.col.f32.bf16.bf16.f32 "
        "{%0,%1,%2,%3}, {%4,%5,%6,%7}, {%8,%9}, {%0,%1,%2,%3};"
        : "+f"(c[0]), "+f"(c[1]), "+f"(c[2]), "+f"(c[3])
        : "r"(a[0]), "r"(a[1]), "r"(a[2]), "r"(a[3]), "r"(b0), "r"(b1));
}

__device__ __forceinline__ void lvl_addrs(const float4* __restrict__ tab,
                                          int res, float u, float v,
                                          const float4*& p00, const float4*& p10,
                                          const float4*& p01, const float4*& p11) {
    float sx = u * (float)res, sy = v * (float)res;
    int x0 = max(0, min((int)sx, res));
    int y0 = max(0, min((int)sy, res));
    int x1 = min(x0 + 1, res), y1 = min(y0 + 1, res);
    int r0 = y0 * res, r1 = y1 * res;      // reference row stride == res
    p00 = tab + r0 + x0; p10 = tab + r0 + x1;
    p01 = tab + r1 + x0; p11 = tab + r1 + x1;
}

__device__ __forceinline__ float4 blend(float4 v00, float4 v10, float4 v01,
                                        float4 v11, int res, float u, float v) {
    float sx = u * (float)res, sy = v * (float)res;
    int x0 = (int)sx, y0 = (int)sy;
    float wx = sx - (float)x0, wy = sy - (float)y0;
    float omwx = 1.0f - wx, omwy = 1.0f - wy;
    float4 o; float t, c;
    t = v00.x*omwx + v10.x*wx; c = v01.x*omwx + v11.x*wx; o.x = t*omwy + c*wy;
    t = v00.y*omwx + v10.y*wx; c = v01.y*omwx + v11.y*wx; o.y = t*omwy + c*wy;
    t = v00.z*omwx + v10.z*wx; c = v01.z*omwx + v11.z*wx; o.z = t*omwy + c*wy;
    t = v00.w*omwx + v10.w*wx; c = v01.w*omwx + v11.w*wx; o.w = t*omwy + c*wy;
    return o;
}

// layer-1 weight, permuted K (matches A0 kpair layout); k==14 -> bias row.
__device__ __forceinline__ float w1val(const float* w1, const float* b1,
                                       int k, int nn) {
    if (k < 5)  return w1[k * 64 + nn];
    if (k == 5 || k == 15) return 0.0f;
    if (k <= 13) return w1[(k - 1) * 64 + nn];
    return b1[nn];
}

__global__ __launch_bounds__(THREADS, 3)
void densegrid_kernel(const float* __restrict__ x,
                      const float4* __restrict__ emb0,
                      const float4* __restrict__ emb1,
                      const float4* __restrict__ emb2,
                      const float* __restrict__ w1, const float* __restrict__ b1,
                      const float* __restrict__ w2, const float* __restrict__ b2,
                      const float* __restrict__ w3, const float* __restrict__ b3,
                      float* __restrict__ out, int n) {
    extern __shared__ char smraw[];
    Smem& s = *reinterpret_cast<Smem*>(smraw);

    const int tid  = threadIdx.x;
    const int wid  = tid >> 5;
    const int lane = tid & 31;
    const int grp  = lane >> 2;
    const int t4   = lane & 3;
    const int p    = lane >> 1;     // gather point within warp-tile
    const int h    = lane & 1;      // gather half

    // ---- one-time weight fragment staging ----
    for (int i = tid; i < 32 * 32; i += THREADS) {
        int ln = i & 31, gkk = i >> 5;
        int kk = gkk & 3, g = gkk >> 2;
        int tt = ln & 3, gp = ln >> 2;
        int nn = 8 * g + gp, k0 = 16 * kk + 2 * tt;
        uint32_t h0 = 0, l0 = 0, h1 = 0, l1 = 0;
        splitval(w2[(k0 + 0) * 64 + nn], 0,  h0, l0);
        splitval(w2[(k0 + 1) * 64 + nn], 16, h0, l0);
        splitval(w2[(k0 + 8) * 64 + nn], 0,  h1, l1);
        splitval(w2[(k0 + 9) * 64 + nn], 16, h1, l1);
        s.B2[i] = make_uint4(h0, h1, l0, l1);
    }
    for (int i = tid; i < 8 * 32; i += THREADS) {
        int ln = i & 31, g = i >> 5;
        int tt = ln & 3, gp = ln >> 2;
        int nn = 8 * g + gp, k0 = 2 * tt;
        uint32_t h0 = 0, l0 = 0, h1 = 0, l1 = 0;
        splitval(w1val(w1, b1, k0 + 0, nn), 0,  h0, l0);
        splitval(w1val(w1, b1, k0 + 1, nn), 16, h0, l0);
        splitval(w1val(w1, b1, k0 + 8, nn), 0,  h1, l1);
        splitval(w1val(w1, b1, k0 + 9, nn), 16, h1, l1);
        s.B1[i] = make_uint4(h0, h1, l0, l1);
    }
    for (int i = tid; i < 4 * 32; i += THREADS) {
        int ln = i & 31, kk = i >> 5;
        int tt = ln & 3, gp = ln >> 2;
        int k0 = 16 * kk + 2 * tt;
        uint32_t h0 = 0, l0 = 0, h1 = 0, l1 = 0;
        if (gp < 3) {
            splitval(w3[(k0 + 0) * 3 + gp], 0,  h0, l0);
            splitval(w3[(k0 + 1) * 3 + gp], 16, h0, l0);
            splitval(w3[(k0 + 8) * 3 + gp], 0,  h1, l1);
            splitval(w3[(k0 + 9) * 3 + gp], 16, h1, l1);
        }
        s.B3[i] = make_uint4(h0, h1, l0, l1);
    }
    for (int i = tid; i < 64; i += THREADS) s.b2s[i] = b2[i];
    if (tid < 8) s.b3s[tid] = (tid < 3) ? b3[tid] : 0.0f;
    __syncthreads();

    // warp-private: constant bias row (kpair 7) of A0
    if (lane < 16) {
        s.A0h[wid][7 * AS + lane] = 0x00003F80u;   // bf16(1.0) low half
        s.A0l[wid][7 * AS + lane] = 0u;
    }
    __syncwarp();

    const int ntw = (n + 15) >> 4;               // warp-tiles
    const int wstride = gridDim.x * 8;
    const int gw = blockIdx.x * 8 + wid;

    // ---- prologue: uv(t0) + issue gathers for first warp-tile ----
    int t = gw;
    float u = 0.f, v = 0.f, idf = 0.f;
    if (t < ntw) {
        int idx = min(t * 16 + p, n - 1);
        u = x[idx * 3 + 1];
        v = x[idx * 3 + 2];
        if (h == 0) idf = x[idx * 3 + 0];
        uint32_t gb = smaddr(&s.G[wid][p * GQ]);
        const float4 *a, *b, *c, *d;
        if (h == 0) {
            lvl_addrs(emb0, 512, u, v, a, b, c, d);
            CPA16(gb +  0, a); CPA16(gb + 16, b);
            CPA16(gb + 32, c); CPA16(gb + 48, d);
            lvl_addrs(emb1, 264, u, v, a, b, c, d);
            CPA16(gb + 64, a); CPA16(gb + 80, b);
        } else {
            lvl_addrs(emb1, 264, u, v, a, b, c, d);
            CPA16(gb +  96, c); CPA16(gb + 112, d);
            lvl_addrs(emb2, 16, u, v, a, b, c, d);
            CPA16(gb + 128, a); CPA16(gb + 144, b);
            CPA16(gb + 160, c); CPA16(gb + 176, d);
        }
    }
    CPA_COMMIT();

    for (; t < ntw; t += wstride) {
        const int tn = t + wstride;

        // early LDG of next tile's coords (latency hidden under blend)
        float un = 0.f, vn = 0.f, idfn = 0.f;
        if (tn < ntw) {
            int idxn = min(tn * 16 + p, n - 1);
            un = x[idxn * 3 + 1];
            vn = x[idxn * 3 + 2];
            if (h == 0) idfn = x[idxn * 3 + 0];
        }

        CPA_WAIT_ALL();
        __syncwarp();   // prior iteration's A0 frag reads complete

        // ---- blend staged texels -> pre-split A0 slice ----
        {
            const float4* g = &s.G[wid][p * GQ];
            uint32_t hh, ll;
            uint32_t* Ah = s.A0h[wid];
            uint32_t* Al = s.A0l[wid];
            if (h == 0) {
                float4 f0 = blend(g[0], g[1], g[2], g[3], 512, u, v);
                splitpack(idf, f0.x, hh, ll);  Ah[0 * AS + p] = hh; Al[0 * AS + p] = ll;
                splitpack(f0.y, f0.z, hh, ll); Ah[1 * AS + p] = hh; Al[1 * AS + p] = ll;
                splitpack(f0.w, 0.0f, hh, ll); Ah[2 * AS + p] = hh; Al[2 * AS + p] = ll;
            } else {
                float4 f1 = blend(g[4], g[5], g[6], g[7], 264, u, v);
                float4 f2 = blend(g[8], g[9], g[10], g[11], 16, u, v);
                splitpack(f1.x, f1.y, hh, ll); Ah[3 * AS + p] = hh; Al[3 * AS + p] = ll;
                splitpack(f1.z, f1.w, hh, ll); Ah[4 * AS + p] = hh; Al[4 * AS + p] = ll;
                splitpack(f2.x, f2.y, hh, ll); Ah[5 * AS + p] = hh; Al[5 * AS + p] = ll;
                splitpack(f2.z, f2.w, hh, ll); Ah[6 * AS + p] = hh; Al[6 * AS + p] = ll;
            }
        }
        __syncwarp();

        // ---- A0 fragments (conflict-free LDS.32) ----
        uint32_t a0h[4], a0l[4];
        {
            const uint32_t* Ah = s.A0h[wid];
            const uint32_t* Al = s.A0l[wid];
            a0h[0] = Ah[t4 * AS + grp];           a0l[0] = Al[t4 * AS + grp];
            a0h[1] = Ah[t4 * AS + grp + 8];       a0l[1] = Al[t4 * AS + grp + 8];
            a0h[2] = Ah[(t4 + 4) * AS + grp];     a0l[2] = Al[(t4 + 4) * AS + grp];
            a0h[3] = Ah[(t4 + 4) * AS + grp + 8]; a0l[3] = Al[(t4 + 4) * AS + grp + 8];
        }

        // ---- issue prefetch for tile tn (overlaps with MMA below) ----
        if (tn < ntw) {
            uint32_t gb = smaddr(&s.G[wid][p * GQ]);
            const float4 *a, *b, *c, *d;
            if (h == 0) {
                lvl_addrs(emb0, 512, un, vn, a, b, c, d);
                CPA16(gb +  0, a); CPA16(gb + 16, b);
                CPA16(gb + 32, c); CPA16(gb + 48, d);
                lvl_addrs(emb1, 264, un, vn, a, b, c, d);
                CPA16(gb + 64, a); CPA16(gb + 80, b);
            } else {
                lvl_addrs(emb1, 264, un, vn, a, b, c, d);
                CPA16(gb +  96, c); CPA16(gb + 112, d);
                lvl_addrs(emb2, 16, un, vn, a, b, c, d);
                CPA16(gb + 128, a); CPA16(gb + 144, b);
                CPA16(gb + 160, c); CPA16(gb + 176, d);
            }
        }
        CPA_COMMIT();
        u = un; v = vn; idf = idfn;

        // ---- layer 1: 16 -> 64 (bias row folded), relu -> A1 frags ----
        uint32_t a1h[4][4], a1l[4][4];
        #pragma unroll
        for (int g = 0; g < 8; g++) {
            float c[4] = {0.0f, 0.0f, 0.0f, 0.0f};
            uint4 b = s.B1[g * 32 + lane];
            mma16816(c, a0h, b.x, b.y);
            mma16816(c, a0h, b.z, b.w);
            mma16816(c, a0l, b.x, b.y);
            int kk = g >> 1, hf = g & 1;
            splitpack(fmaxf(c[0], 0.0f), fmaxf(c[1], 0.0f),
                      a1h[kk][2 * hf + 0], a1l[kk][2 * hf + 0]);
            splitpack(fmaxf(c[2], 0.0f), fmaxf(c[3], 0.0f),
                      a1h[kk][2 * hf + 1], a1l[kk][2 * hf + 1]);
        }

        // ---- layer 2: 64 -> 64, bias+relu -> A2 frags ----
        uint32_t a2h[4][4], a2l[4][4];
        #pragma unroll
        for (int g = 0; g < 8; g++) {
            float c[4];
            float2 bb = *(const float2*)&s.b2s[8 * g + 2 * t4];
            c[0] = bb.x; c[1] = bb.y; c[2] = bb.x; c[3] = bb.y;
            #pragma unroll
            for (int kk = 0; kk < 4; kk++) {
                uint4 b = s.B2[(g * 4 + kk) * 32 + lane];
                mma16816(c, a1h[kk], b.x, b.y);
                mma16816(c, a1h[kk], b.z, b.w);
                mma16816(c, a1l[kk], b.x, b.y);
            }
            int kk2 = g >> 1, hf = g & 1;
            splitpack(fmaxf(c[0], 0.0f), fmaxf(c[1], 0.0f),
                      a2h[kk2][2 * hf + 0], a2l[kk2][2 * hf + 0]);
            splitpack(fmaxf(c[2], 0.0f), fmaxf(c[3], 0.0f),
                      a2h[kk2][2 * hf + 1], a2l[kk2][2 * hf + 1]);
        }

        // ---- layer 3: 64 -> 8 (3 used), write output ----
        {
            float c[4];
            float2 bb = *(const float2*)&s.b3s[2 * t4];
            c[0] = bb.x; c[1] = bb.y; c[2] = bb.x; c[3] = bb.y;
            #pragma unroll
            for (int kk = 0; kk < 4; kk++) {
                uint4 b = s.B3[kk * 32 + lane];
                mma16816(c, a2h[kk], b.x, b.y);
                mma16816(c, a2h[kk], b.z, b.w);
                mma16816(c, a2l[kk], b.x, b.y);
            }
            int p0 = t * 16 + grp;
            int col = 2 * t4;
            if (col < 3) {
                if (p0 < n)     out[p0 * 3 + col]       = c[0];
                if (p0 + 8 < n) out[(p0 + 8) * 3 + col] = c[2];
            }
            if (col + 1 < 3) {
                if (p0 < n)     out[p0 * 3 + col + 1]       = c[1];
                if (p0 + 8 < n) out[(p0 + 8) * 3 + col + 1] = c[3];
            }
        }
    }
}

extern "C" void kernel_launch(void* const* d_in, const int* in_sizes, int n_in,
                              void* d_out, int out_size) {
    const float* x    = (const float*)d_in[0];
    const float4* e0  = (const float4*)d_in[1];
    const float4* e1  = (const float4*)d_in[2];
    const float4* e2  = (const float4*)d_in[3];
    const float* w1   = (const float*)d_in[4];
    const float* b1   = (const float*)d_in[5];
    const float* w2   = (const float*)d_in[6];
    const float* b2   = (const float*)d_in[7];
    const float* w3   = (const float*)d_in[8];
    const float* b3   = (const float*)d_in[9];
    float* out        = (float*)d_out;
    int n = in_sizes[0] / 3;
    (void)n_in; (void)out_size;
    cudaFuncSetAttribute(densegrid_kernel,
                         cudaFuncAttributeMaxDynamicSharedMemorySize, SMEM_BYTES);
    densegrid_kernel<<<NCTA, THREADS, SMEM_BYTES>>>(
        x, e0, e1, e2, w1, b1, w2, b2, w3, b3, out, n);
}

// round 14
// speedup vs baseline: 1.0448x; 1.0448x over previous
#include <cuda_runtime.h>
#include <cuda_bf16.h>
#include <cstdint>

// DenseGridNet via warp-level mma.sync bf16 (m16n8k16), split-bf16 x3.
// R14: lane-cooperative gather — 4 texels of a point land in 4 lanes of ONE
// LDG.128 instruction so same-128B-line texel pairs coalesce into one L1
// wavefront (halves gather L1 traffic); bilinear blend via shfl.bfly
// butterflies. Warp-owned 16-point tiles, __syncwarp only; R12 MMA pipeline.

#define THREADS 256
#define NCTA 444
#define AS 24    // A0 slice row stride (words) -> conflict-free frag ld/st

__device__ __forceinline__ void splitpack(float v0, float v1,
                                          uint32_t& hi, uint32_t& lo) {
    asm("cvt.rn.bf16x2.f32 %0, %1, %2;" : "=r"(hi) : "f"(v1), "f"(v0));
    float r0 = __uint_as_float(hi << 16);
    float r1 = __uint_as_float(hi & 0xFFFF0000u);
    asm("cvt.rn.bf16x2.f32 %0, %1, %2;" : "=r"(lo) : "f"(v1 - r1), "f"(v0 - r0));
}
__device__ __forceinline__ void splitval(float v, uint32_t pos16,
                                         uint32_t& hi, uint32_t& lo) {
    __nv_bfloat16 h = __float2bfloat16(v);
    float r = v - __bfloat162float(h);
    __nv_bfloat16 l = __float2bfloat16(r);
    uint16_t hb, lb;
    __builtin_memcpy(&hb, &h, 2);
    __builtin_memcpy(&lb, &l, 2);
    hi |= (uint32_t)hb << pos16;
    lo |= (uint32_t)lb << pos16;
}

__device__ __forceinline__ void mma16816(float c[4], const uint32_t a[4],
                                         uint32_t b0, uint32_t b1) {
    asm volatile(
        "mma.sync.aligned.m16n8k16.row.col.f32.bf16.bf16.f32 "
        "{%0,%1,%2,%3}, {%4,%5,%6,%7}, {%8,%9}, {%0,%1,%2,%3};"
        : "+f"(c[0]), "+f"(c[1]), "+f"(c[2]), "+f"(c[3])
        : "r"(a[0]), "r"(a[1]), "r"(a[2]), "r"(a[3]), "r"(b0), "r"(b1));
}

// texel for this lane: t4 bit0 selects x0/x1, bit1 selects y0/y1
__device__ __forceinline__ float4 lvl_tex(const float4* __restrict__ tab,
                                          int res, float u, float v, int t4) {
    float sx = u * (float)res, sy = v * (float)res;
    int x0 = (int)sx, y0 = (int)sy;            // truncation == astype(int32)
    int x1 = min(x0 + 1, res), y1 = min(y0 + 1, res);
    int xi = (t4 & 1) ? x1 : x0;
    int yi = (t4 & 2) ? y1 : y0;
    return tab[yi * res + xi];                 // reference row stride == res
}

// 2-stage butterfly bilinear blend; after this all 4 lanes of the quad hold f
__device__ __forceinline__ float4 blend_shfl(float4 t, int res,
                                             float u, float v, int t4) {
    float sx = u * (float)res, sy = v * (float)res;
    float wx = sx - (float)(int)sx;
    float wy = sy - (float)(int)sy;
    float mx = (t4 & 1) ? wx : (1.0f - wx);
    float my = (t4 & 2) ? wy : (1.0f - wy);
    float4 c;
    c.x = t.x * mx; c.y = t.y * mx; c.z = t.z * mx; c.w = t.w * mx;
    c.x += __shfl_xor_sync(0xffffffffu, c.x, 1);
    c.y += __shfl_xor_sync(0xffffffffu, c.y, 1);
    c.z += __shfl_xor_sync(0xffffffffu, c.z, 1);
    c.w += __shfl_xor_sync(0xffffffffu, c.w, 1);
    c.x *= my; c.y *= my; c.z *= my; c.w *= my;
    c.x += __shfl_xor_sync(0xffffffffu, c.x, 2);
    c.y += __shfl_xor_sync(0xffffffffu, c.y, 2);
    c.z += __shfl_xor_sync(0xffffffffu, c.z, 2);
    c.w += __shfl_xor_sync(0xffffffffu, c.w, 2);
    return c;
}

// layer-1 weight, permuted K (matches A0 kpair layout); k==14 -> bias row.
__device__ __forceinline__ float w1val(const float* w1, const float* b1,
                                       int k, int nn) {
    if (k < 5)  return w1[k * 64 + nn];
    if (k == 5 || k == 15) return 0.0f;
    if (k <= 13) return w1[(k - 1) * 64 + nn];
    return b1[nn];
}

__global__ __launch_bounds__(THREADS, 3)
void densegrid_kernel(const float* __restrict__ x,
                      const float4* __restrict__ emb0,
                      const float4* __restrict__ emb1,
                      const float4* __restrict__ emb2,
                      const float* __restrict__ w1, const float* __restrict__ b1,
                      const float* __restrict__ w2, const float* __restrict__ b2,
                      const float* __restrict__ w3, const float* __restrict__ b3,
                      float* __restrict__ out, int n) {
    __shared__ uint4 B1[8 * 32];
    __shared__ uint4 B2[32 * 32];
    __shared__ uint4 B3[4 * 32];
    __shared__ float b2s[64], b3s[8];
    __shared__ uint32_t A0h[8][8 * AS];
    __shared__ uint32_t A0l[8][8 * AS];

    const int tid  = threadIdx.x;
    const int wid  = tid >> 5;
    const int lane = tid & 31;
    const int grp  = lane >> 2;
    const int t4   = lane & 3;

    // ---- one-time weight fragment staging ----
    for (int i = tid; i < 32 * 32; i += THREADS) {
        int ln = i & 31, gkk = i >> 5;
        int kk = gkk & 3, g = gkk >> 2;
        int tt = ln & 3, gp = ln >> 2;
        int nn = 8 * g + gp, k0 = 16 * kk + 2 * tt;
        uint32_t h0 = 0, l0 = 0, h1 = 0, l1 = 0;
        splitval(w2[(k0 + 0) * 64 + nn], 0,  h0, l0);
        splitval(w2[(k0 + 1) * 64 + nn], 16, h0, l0);
        splitval(w2[(k0 + 8) * 64 + nn], 0,  h1, l1);
        splitval(w2[(k0 + 9) * 64 + nn], 16, h1, l1);
        B2[i] = make_uint4(h0, h1, l0, l1);
    }
    for (int i = tid; i < 8 * 32; i += THREADS) {
        int ln = i & 31, g = i >> 5;
        int tt = ln & 3, gp = ln >> 2;
        int nn = 8 * g + gp, k0 = 2 * tt;
        uint32_t h0 = 0, l0 = 0, h1 = 0, l1 = 0;
        splitval(w1val(w1, b1, k0 + 0, nn), 0,  h0, l0);
        splitval(w1val(w1, b1, k0 + 1, nn), 16, h0, l0);
        splitval(w1val(w1, b1, k0 + 8, nn), 0,  h1, l1);
        splitval(w1val(w1, b1, k0 + 9, nn), 16, h1, l1);
        B1[i] = make_uint4(h0, h1, l0, l1);
    }
    for (int i = tid; i < 4 * 32; i += THREADS) {
        int ln = i & 31, kk = i >> 5;
        int tt = ln & 3, gp = ln >> 2;
        int k0 = 16 * kk + 2 * tt;
        uint32_t h0 = 0, l0 = 0, h1 = 0, l1 = 0;
        if (gp < 3) {
            splitval(w3[(k0 + 0) * 3 + gp], 0,  h0, l0);
            splitval(w3[(k0 + 1) * 3 + gp], 16, h0, l0);
            splitval(w3[(k0 + 8) * 3 + gp], 0,  h1, l1);
            splitval(w3[(k0 + 9) * 3 + gp], 16, h1, l1);
        }
        B3[i] = make_uint4(h0, h1, l0, l1);
    }
    for (int i = tid; i < 64; i += THREADS) b2s[i] = b2[i];
    if (tid < 8) b3s[tid] = (tid < 3) ? b3[tid] : 0.0f;
    __syncthreads();

    // warp-private constant bias row (kpair 7)
    if (lane < 16) {
        A0h[wid][7 * AS + lane] = 0x00003F80u;   // bf16(1.0) low half
        A0l[wid][7 * AS + lane] = 0u;
    }
    __syncwarp();

    const int ntw = (n + 15) >> 4;
    const int wstride = gridDim.x * 8;

    for (int wt = blockIdx.x * 8 + wid; wt < ntw; wt += wstride) {
        __syncwarp();   // prior tile's A0 frag reads complete

        // ---- lane-cooperative gather: 2 rounds of 8 points ----
        int i0 = min(wt * 16 + grp, n - 1);
        int i1 = min(wt * 16 + 8 + grp, n - 1);
        float id0 = x[i0 * 3 + 0], u0 = x[i0 * 3 + 1], v0 = x[i0 * 3 + 2];
        float id1 = x[i1 * 3 + 0], u1 = x[i1 * 3 + 1], v1 = x[i1 * 3 + 2];
        // issue all 6 texel loads (independent, MLP=6)
        float4 t00 = lvl_tex(emb0, 512, u0, v0, t4);
        float4 t01 = lvl_tex(emb1, 264, u0, v0, t4);
        float4 t02 = lvl_tex(emb2, 16,  u0, v0, t4);
        float4 t10 = lvl_tex(emb0, 512, u1, v1, t4);
        float4 t11 = lvl_tex(emb1, 264, u1, v1, t4);
        float4 t12 = lvl_tex(emb2, 16,  u1, v1, t4);

        uint32_t* Ah = A0h[wid];
        uint32_t* Al = A0l[wid];
        #pragma unroll
        for (int r = 0; r < 2; r++) {
            float idf = r ? id1 : id0;
            float u = r ? u1 : u0, v = r ? v1 : v0;
            float4 f0 = blend_shfl(r ? t10 : t00, 512, u, v, t4);
            float4 f1 = blend_shfl(r ? t11 : t01, 264, u, v, t4);
            float4 f2 = blend_shfl(r ? t12 : t02, 16,  u, v, t4);
            int p8 = r * 8 + grp;
            uint32_t hh, ll;
            if (t4 == 0) {
                splitpack(idf, f0.x, hh, ll);
                Ah[0 * AS + p8] = hh; Al[0 * AS + p8] = ll;
                splitpack(f1.z, f1.w, hh, ll);
                Ah[4 * AS + p8] = hh; Al[4 * AS + p8] = ll;
            } else if (t4 == 1) {
                splitpack(f0.y, f0.z, hh, ll);
                Ah[1 * AS + p8] = hh; Al[1 * AS + p8] = ll;
                splitpack(f2.x, f2.y, hh, ll);
                Ah[5 * AS + p8] = hh; Al[5 * AS + p8] = ll;
            } else if (t4 == 2) {
                splitpack(f0.w, 0.0f, hh, ll);
                Ah[2 * AS + p8] = hh; Al[2 * AS + p8] = ll;
                splitpack(f2.z, f2.w, hh, ll);
                Ah[6 * AS + p8] = hh; Al[6 * AS + p8] = ll;
            } else {
                splitpack(f1.x, f1.y, hh, ll);
                Ah[3 * AS + p8] = hh; Al[3 * AS + p8] = ll;
            }
        }
        __syncwarp();

        // ---- A0 fragments (conflict-free LDS.32) ----
        uint32_t a0h[4], a0l[4];
        a0h[0] = Ah[t4 * AS + grp];           a0l[0] = Al[t4 * AS + grp];
        a0h[1] = Ah[t4 * AS + grp + 8];       a0l[1] = Al[t4 * AS + grp + 8];
        a0h[2] = Ah[(t4 + 4) * AS + grp];     a0l[2] = Al[(t4 + 4) * AS + grp];
        a0h[3] = Ah[(t4 + 4) * AS + grp + 8]; a0l[3] = Al[(t4 + 4) * AS + grp + 8];

        // ---- layer 1: 16 -> 64 (bias row folded), relu -> A1 frags ----
        uint32_t a1h[4][4], a1l[4][4];
        #pragma unroll
        for (int g = 0; g < 8; g++) {
            float c[4] = {0.0f, 0.0f, 0.0f, 0.0f};
            uint4 b = B1[g * 32 + lane];
            mma16816(c, a0h, b.x, b.y);
            mma16816(c, a0h, b.z, b.w);
            mma16816(c, a0l, b.x, b.y);
            int kk = g >> 1, hf = g & 1;
            splitpack(fmaxf(c[0], 0.0f), fmaxf(c[1], 0.0f),
                      a1h[kk][2 * hf + 0], a1l[kk][2 * hf + 0]);
            splitpack(fmaxf(c[2], 0.0f), fmaxf(c[3], 0.0f),
                      a1h[kk][2 * hf + 1], a1l[kk][2 * hf + 1]);
        }

        // ---- layer 2: 64 -> 64, bias+relu -> A2 frags ----
        uint32_t a2h[4][4], a2l[4][4];
        #pragma unroll
        for (int g = 0; g < 8; g++) {
            float c[4];
            float2 bb = *(const float2*)&b2s[8 * g + 2 * t4];
            c[0] = bb.x; c[1] = bb.y; c[2] = bb.x; c[3] = bb.y;
            #pragma unroll
            for (int kk = 0; kk < 4; kk++) {
                uint4 b = B2[(g * 4 + kk) * 32 + lane];
                mma16816(c, a1h[kk], b.x, b.y);
                mma16816(c, a1h[kk], b.z, b.w);
                mma16816(c, a1l[kk], b.x, b.y);
            }
            int kk2 = g >> 1, hf = g & 1;
            splitpack(fmaxf(c[0], 0.0f), fmaxf(c[1], 0.0f),
                      a2h[kk2][2 * hf + 0], a2l[kk2][2 * hf + 0]);
            splitpack(fmaxf(c[2], 0.0f), fmaxf(c[3], 0.0f),
                      a2h[kk2][2 * hf + 1], a2l[kk2][2 * hf + 1]);
        }

        // ---- layer 3: 64 -> 8 (3 used), write output ----
        {
            float c[4];
            float2 bb = *(const float2*)&b3s[2 * t4];
            c[0] = bb.x; c[1] = bb.y; c[2] = bb.x; c[3] = bb.y;
            #pragma unroll
            for (int kk = 0; kk < 4; kk++) {
                uint4 b = B3[kk * 32 + lane];
                mma16816(c, a2h[kk], b.x, b.y);
                mma16816(c, a2h[kk], b.z, b.w);
                mma16816(c, a2l[kk], b.x, b.y);
            }
            int p0 = wt * 16 + grp;
            int col = 2 * t4;
            if (col < 3) {
                if (p0 < n)     out[p0 * 3 + col]       = c[0];
                if (p0 + 8 < n) out[(p0 + 8) * 3 + col] = c[2];
            }
            if (col + 1 < 3) {
                if (p0 < n)     out[p0 * 3 + col + 1]       = c[1];
                if (p0 + 8 < n) out[(p0 + 8) * 3 + col + 1] = c[3];
            }
        }
    }
}

extern "C" void kernel_launch(void* const* d_in, const int* in_sizes, int n_in,
                              void* d_out, int out_size) {
    const float* x    = (const float*)d_in[0];
    const float4* e0  = (const float4*)d_in[1];
    const float4* e1  = (const float4*)d_in[2];
    const float4* e2  = (const float4*)d_in[3];
    const float* w1   = (const float*)d_in[4];
    const float* b1   = (const float*)d_in[5];
    const float* w2   = (const float*)d_in[6];
    const float* b2   = (const float*)d_in[7];
    const float* w3   = (const float*)d_in[8];
    const float* b3   = (const float*)d_in[9];
    float* out        = (float*)d_out;
    int n = in_sizes[0] / 3;
    (void)n_in; (void)out_size;
    densegrid_kernel<<<NCTA, THREADS>>>(
        x, e0, e1, e2, w1, b1, w2, b2, w3, b3, out, n);
}

// round 15
// speedup vs baseline: 1.0845x; 1.0380x over previous
#include <cuda_runtime.h>
#include <cuda_bf16.h>
#include <cstdint>

// DenseGridNet via warp-level mma.sync bf16 (m16n8k16), split-bf16 x3.
// R15: warp-autonomous tiles + lane-cooperative cp.async gather (quad lanes
// fetch the 4 bilerp corners -> same-128B-line pairs coalesce) staged one
// warp-tile ahead into warp-private smem; uniform per-point-pair blend (R13
// style, no shfl / no divergent split); x coords register-prefetched.

#define THREADS 256
#define NCTA 444
#define AS 24    // A0 slice row stride (words) -> conflict-free frag ld/st
#define GQ 13    // staged quads per point (12 used + 1 pad)

struct __align__(16) Smem {
    uint4 B1[8 * 32];
    uint4 B2[32 * 32];
    uint4 B3[4 * 32];
    float b2s[64], b3s[8];
    uint32_t A0h[8][8 * AS];
    uint32_t A0l[8][8 * AS];
    float4 G[8][16 * GQ];     // per-warp staged texels
};
#define SMEM_BYTES ((int)sizeof(Smem))

__device__ __forceinline__ uint32_t smaddr(const void* p) {
    uint32_t a;
    asm("{ .reg .u64 t; cvta.to.shared.u64 t, %1; cvt.u32.u64 %0, t; }"
        : "=r"(a) : "l"(p));
    return a;
}
#define CPA16(sm, gm) \
    asm volatile("cp.async.ca.shared.global [%0], [%1], 16;" \
                 :: "r"(sm), "l"(gm) : "memory")
#define CPA_COMMIT()   asm volatile("cp.async.commit_group;" ::: "memory")
#define CPA_WAIT_ALL() asm volatile("cp.async.wait_group 0;" ::: "memory")

__device__ __forceinline__ void splitpack(float v0, float v1,
                                          uint32_t& hi, uint32_t& lo) {
    asm("cvt.rn.bf16x2.f32 %0, %1, %2;" : "=r"(hi) : "f"(v1), "f"(v0));
    float r0 = __uint_as_float(hi << 16);
    float r1 = __uint_as_float(hi & 0xFFFF0000u);
    asm("cvt.rn.bf16x2.f32 %0, %1, %2;" : "=r"(lo) : "f"(v1 - r1), "f"(v0 - r0));
}
__device__ __forceinline__ void splitval(float v, uint32_t pos16,
                                         uint32_t& hi, uint32_t& lo) {
    __nv_bfloat16 h = __float2bfloat16(v);
    float r = v - __bfloat162float(h);
    __nv_bfloat16 l = __float2bfloat16(r);
    uint16_t hb, lb;
    __builtin_memcpy(&hb, &h, 2);
    __builtin_memcpy(&lb, &l, 2);
    hi |= (uint32_t)hb << pos16;
    lo |= (uint32_t)lb << pos16;
}

__device__ __forceinline__ void mma16816(float c[4], const uint32_t a[4],
                                         uint32_t b0, uint32_t b1) {
    asm volatile(
        "mma.sync.aligned.m16n8k16.row.col.f32.bf16.bf16.f32 "
        "{%0,%1,%2,%3}, {%4,%5,%6,%7}, {%8,%9}, {%0,%1,%2,%3};"
        : "+f"(c[0]), "+f"(c[1]), "+f"(c[2]), "+f"(c[3])
        : "r"(a[0]), "r"(a[1]), "r"(a[2]), "r"(a[3]), "r"(b0), "r"(b1));
}

// gmem address of this lane's bilerp corner (t4 bit0 -> x1, bit1 -> y1)
__device__ __forceinline__ const float4* tex_addr(const float4* __restrict__ tab,
                                                  int res, float u, float v,
                                                  int t4) {
    float sx = u * (float)res, sy = v * (float)res;
    int x0 = (int)sx, y0 = (int)sy;            // truncation == astype(int32)
    int xi = (t4 & 1) ? min(x0 + 1, res) : min(x0, res);
    int yi = (t4 & 2) ? min(y0 + 1, res) : min(y0, res);
    return tab + yi * res + xi;                // reference row stride == res
}

// reference-exact bilinear combine of staged texels
__device__ __forceinline__ float4 blend(float4 v00, float4 v10, float4 v01,
                                        float4 v11, int res, float u, float v) {
    float sx = u * (float)res, sy = v * (float)res;
    int x0 = (int)sx, y0 = (int)sy;
    float wx = sx - (float)x0, wy = sy - (float)y0;
    float omwx = 1.0f - wx, omwy = 1.0f - wy;
    float4 o; float t, c;
    t = v00.x*omwx + v10.x*wx; c = v01.x*omwx + v11.x*wx; o.x = t*omwy + c*wy;
    t = v00.y*omwx + v10.y*wx; c = v01.y*omwx + v11.y*wx; o.y = t*omwy + c*wy;
    t = v00.z*omwx + v10.z*wx; c = v01.z*omwx + v11.z*wx; o.z = t*omwy + c*wy;
    t = v00.w*omwx + v10.w*wx; c = v01.w*omwx + v11.w*wx; o.w = t*omwy + c*wy;
    return o;
}

// layer-1 weight, permuted K (matches A0 kpair layout); k==14 -> bias row.
__device__ __forceinline__ float w1val(const float* w1, const float* b1,
                                       int k, int nn) {
    if (k < 5)  return w1[k * 64 + nn];
    if (k == 5 || k == 15) return 0.0f;
    if (k <= 13) return w1[(k - 1) * 64 + nn];
    return b1[nn];
}

__global__ __launch_bounds__(THREADS, 3)
void densegrid_kernel(const float* __restrict__ x,
                      const float4* __restrict__ emb0,
                      const float4* __restrict__ emb1,
                      const float4* __restrict__ emb2,
                      const float* __restrict__ w1, const float* __restrict__ b1,
                      const float* __restrict__ w2, const float* __restrict__ b2,
                      const float* __restrict__ w3, const float* __restrict__ b3,
                      float* __restrict__ out, int n) {
    extern __shared__ char smraw[];
    Smem& s = *reinterpret_cast<Smem*>(smraw);

    const int tid  = threadIdx.x;
    const int wid  = tid >> 5;
    const int lane = tid & 31;
    const int grp  = lane >> 2;    // MMA row group
    const int t4   = lane & 3;
    const int pb   = lane >> 1;    // blend point (0-15)
    const int hb   = lane & 1;     // blend half-role
    const int pg   = lane >> 2;    // gather point base (0-7)

    // ---- one-time weight fragment staging ----
    for (int i = tid; i < 32 * 32; i += THREADS) {
        int ln = i & 31, gkk = i >> 5;
        int kk = gkk & 3, g = gkk >> 2;
        int tt = ln & 3, gp = ln >> 2;
        int nn = 8 * g + gp, k0 = 16 * kk + 2 * tt;
        uint32_t h0 = 0, l0 = 0, h1 = 0, l1 = 0;
        splitval(w2[(k0 + 0) * 64 + nn], 0,  h0, l0);
        splitval(w2[(k0 + 1) * 64 + nn], 16, h0, l0);
        splitval(w2[(k0 + 8) * 64 + nn], 0,  h1, l1);
        splitval(w2[(k0 + 9) * 64 + nn], 16, h1, l1);
        s.B2[i] = make_uint4(h0, h1, l0, l1);
    }
    for (int i = tid; i < 8 * 32; i += THREADS) {
        int ln = i & 31, g = i >> 5;
        int tt = ln & 3, gp = ln >> 2;
        int nn = 8 * g + gp, k0 = 2 * tt;
        uint32_t h0 = 0, l0 = 0, h1 = 0, l1 = 0;
        splitval(w1val(w1, b1, k0 + 0, nn), 0,  h0, l0);
        splitval(w1val(w1, b1, k0 + 1, nn), 16, h0, l0);
        splitval(w1val(w1, b1, k0 + 8, nn), 0,  h1, l1);
        splitval(w1val(w1, b1, k0 + 9, nn), 16, h1, l1);
        s.B1[i] = make_uint4(h0, h1, l0, l1);
    }
    for (int i = tid; i < 4 * 32; i += THREADS) {
        int ln = i & 31, kk = i >> 5;
        int tt = ln & 3, gp = ln >> 2;
        int k0 = 16 * kk + 2 * tt;
        uint32_t h0 = 0, l0 = 0, h1 = 0, l1 = 0;
        if (gp < 3) {
            splitval(w3[(k0 + 0) * 3 + gp], 0,  h0, l0);
            splitval(w3[(k0 + 1) * 3 + gp], 16, h0, l0);
            splitval(w3[(k0 + 8) * 3 + gp], 0,  h1, l1);
            splitval(w3[(k0 + 9) * 3 + gp], 16, h1, l1);
        }
        s.B3[i] = make_uint4(h0, h1, l0, l1);
    }
    for (int i = tid; i < 64; i += THREADS) s.b2s[i] = b2[i];
    if (tid < 8) s.b3s[tid] = (tid < 3) ? b3[tid] : 0.0f;
    __syncthreads();

    if (lane < 16) {
        s.A0h[wid][7 * AS + lane] = 0x00003F80u;   // bf16(1.0) bias row
        s.A0l[wid][7 * AS + lane] = 0u;
    }
    __syncwarp();

    const int ntw = (n + 15) >> 4;
    const int wstride = gridDim.x * 8;
    int t = blockIdx.x * 8 + wid;

    // carried coords for tile t
    float ub = 0.f, vb = 0.f, idb = 0.f;         // blend role, point pb
    float ug0 = 0.f, vg0 = 0.f, ug1 = 0.f, vg1 = 0.f;  // gather role, pts pg, 8+pg
    const uint32_t gbase = smaddr(&s.G[wid][0]);

    if (t < ntw) {
        int ib  = min(t * 16 + pb, n - 1);
        idb = x[ib * 3 + 0]; ub = x[ib * 3 + 1]; vb = x[ib * 3 + 2];
        int ig0 = min(t * 16 + pg, n - 1);
        int ig1 = min(t * 16 + 8 + pg, n - 1);
        ug0 = x[ig0 * 3 + 1]; vg0 = x[ig0 * 3 + 2];
        ug1 = x[ig1 * 3 + 1]; vg1 = x[ig1 * 3 + 2];
        // issue lane-cooperative gathers for tile t
        CPA16(gbase + (pg * GQ + 0 + t4) * 16, tex_addr(emb0, 512, ug0, vg0, t4));
        CPA16(gbase + (pg * GQ + 4 + t4) * 16, tex_addr(emb1, 264, ug0, vg0, t4));
        CPA16(gbase + (pg * GQ + 8 + t4) * 16, tex_addr(emb2, 16,  ug0, vg0, t4));
        CPA16(gbase + ((8 + pg) * GQ + 0 + t4) * 16, tex_addr(emb0, 512, ug1, vg1, t4));
        CPA16(gbase + ((8 + pg) * GQ + 4 + t4) * 16, tex_addr(emb1, 264, ug1, vg1, t4));
        CPA16(gbase + ((8 + pg) * GQ + 8 + t4) * 16, tex_addr(emb2, 16,  ug1, vg1, t4));
    }
    CPA_COMMIT();

    for (; t < ntw; t += wstride) {
        const int tn = t + wstride;

        // prefetch coords for tile tn (latency rides under blend + layer1)
        float ubn = 0.f, vbn = 0.f, idbn = 0.f;
        float ug0n = 0.f, vg0n = 0.f, ug1n = 0.f, vg1n = 0.f;
        if (tn < ntw) {
            int ib  = min(tn * 16 + pb, n - 1);
            idbn = x[ib * 3 + 0]; ubn = x[ib * 3 + 1]; vbn = x[ib * 3 + 2];
            int ig0 = min(tn * 16 + pg, n - 1);
            int ig1 = min(tn * 16 + 8 + pg, n - 1);
            ug0n = x[ig0 * 3 + 1]; vg0n = x[ig0 * 3 + 2];
            ug1n = x[ig1 * 3 + 1]; vg1n = x[ig1 * 3 + 2];
        }

        CPA_WAIT_ALL();
        __syncwarp();   // texels staged; prior tile's A0 reads done

        // ---- uniform per-point-pair blend -> pre-split A0 ----
        {
            const float4* g = &s.G[wid][pb * GQ];
            uint32_t* Ah = s.A0h[wid];
            uint32_t* Al = s.A0l[wid];
            uint32_t hh, ll;
            if (hb == 0) {
                float4 f0 = blend(g[0], g[1], g[2], g[3], 512, ub, vb);
                splitpack(idb, f0.x, hh, ll);  Ah[0 * AS + pb] = hh; Al[0 * AS + pb] = ll;
                splitpack(f0.y, f0.z, hh, ll); Ah[1 * AS + pb] = hh; Al[1 * AS + pb] = ll;
                splitpack(f0.w, 0.0f, hh, ll); Ah[2 * AS + pb] = hh; Al[2 * AS + pb] = ll;
            } else {
                float4 f1 = blend(g[4], g[5], g[6], g[7], 264, ub, vb);
                float4 f2 = blend(g[8], g[9], g[10], g[11], 16, ub, vb);
                splitpack(f1.x, f1.y, hh, ll); Ah[3 * AS + pb] = hh; Al[3 * AS + pb] = ll;
                splitpack(f1.z, f1.w, hh, ll); Ah[4 * AS + pb] = hh; Al[4 * AS + pb] = ll;
                splitpack(f2.x, f2.y, hh, ll); Ah[5 * AS + pb] = hh; Al[5 * AS + pb] = ll;
                splitpack(f2.z, f2.w, hh, ll); Ah[6 * AS + pb] = hh; Al[6 * AS + pb] = ll;
            }
        }
        __syncwarp();

        // ---- A0 fragments (conflict-free LDS.32) ----
        uint32_t a0h[4], a0l[4];
        {
            const uint32_t* Ah = s.A0h[wid];
            const uint32_t* Al = s.A0l[wid];
            a0h[0] = Ah[t4 * AS + grp];           a0l[0] = Al[t4 * AS + grp];
            a0h[1] = Ah[t4 * AS + grp + 8];       a0l[1] = Al[t4 * AS + grp + 8];
            a0h[2] = Ah[(t4 + 4) * AS + grp];     a0l[2] = Al[(t4 + 4) * AS + grp];
            a0h[3] = Ah[(t4 + 4) * AS + grp + 8]; a0l[3] = Al[(t4 + 4) * AS + grp + 8];
        }

        // ---- layer 1: 16 -> 64 (bias row folded), relu -> A1 frags ----
        uint32_t a1h[4][4], a1l[4][4];
        #pragma unroll
        for (int g = 0; g < 8; g++) {
            float c[4] = {0.0f, 0.0f, 0.0f, 0.0f};
            uint4 b = s.B1[g * 32 + lane];
            mma16816(c, a0h, b.x, b.y);
            mma16816(c, a0h, b.z, b.w);
            mma16816(c, a0l, b.x, b.y);
            int kk = g >> 1, hf = g & 1;
            splitpack(fmaxf(c[0], 0.0f), fmaxf(c[1], 0.0f),
                      a1h[kk][2 * hf + 0], a1l[kk][2 * hf + 0]);
            splitpack(fmaxf(c[2], 0.0f), fmaxf(c[3], 0.0f),
                      a1h[kk][2 * hf + 1], a1l[kk][2 * hf + 1]);
        }

        // ---- issue cp.async gathers for tile tn (overlaps layers 2/3) ----
        if (tn < ntw) {
            CPA16(gbase + (pg * GQ + 0 + t4) * 16, tex_addr(emb0, 512, ug0n, vg0n, t4));
            CPA16(gbase + (pg * GQ + 4 + t4) * 16, tex_addr(emb1, 264, ug0n, vg0n, t4));
            CPA16(gbase + (pg * GQ + 8 + t4) * 16, tex_addr(emb2, 16,  ug0n, vg0n, t4));
            CPA16(gbase + ((8 + pg) * GQ + 0 + t4) * 16, tex_addr(emb0, 512, ug1n, vg1n, t4));
            CPA16(gbase + ((8 + pg) * GQ + 4 + t4) * 16, tex_addr(emb1, 264, ug1n, vg1n, t4));
            CPA16(gbase + ((8 + pg) * GQ + 8 + t4) * 16, tex_addr(emb2, 16,  ug1n, vg1n, t4));
        }
        CPA_COMMIT();

        // ---- layer 2: 64 -> 64, bias+relu -> A2 frags ----
        uint32_t a2h[4][4], a2l[4][4];
        #pragma unroll
        for (int g = 0; g < 8; g++) {
            float c[4];
            float2 bb = *(const float2*)&s.b2s[8 * g + 2 * t4];
            c[0] = bb.x; c[1] = bb.y; c[2] = bb.x; c[3] = bb.y;
            #pragma unroll
            for (int kk = 0; kk < 4; kk++) {
                uint4 b = s.B2[(g * 4 + kk) * 32 + lane];
                mma16816(c, a1h[kk], b.x, b.y);
                mma16816(c, a1h[kk], b.z, b.w);
                mma16816(c, a1l[kk], b.x, b.y);
            }
            int kk2 = g >> 1, hf = g & 1;
            splitpack(fmaxf(c[0], 0.0f), fmaxf(c[1], 0.0f),
                      a2h[kk2][2 * hf + 0], a2l[kk2][2 * hf + 0]);
            splitpack(fmaxf(c[2], 0.0f), fmaxf(c[3], 0.0f),
                      a2h[kk2][2 * hf + 1], a2l[kk2][2 * hf + 1]);
        }

        // ---- layer 3: 64 -> 8 (3 used), write output ----
        {
            float c[4];
            float2 bb = *(const float2*)&s.b3s[2 * t4];
            c[0] = bb.x; c[1] = bb.y; c[2] = bb.x; c[3] = bb.y;
            #pragma unroll
            for (int kk = 0; kk < 4; kk++) {
                uint4 b = s.B3[kk * 32 + lane];
                mma16816(c, a2h[kk], b.x, b.y);
                mma16816(c, a2h[kk], b.z, b.w);
                mma16816(c, a2l[kk], b.x, b.y);
            }
            int p0 = t * 16 + grp;
            int col = 2 * t4;
            if (col < 3) {
                if (p0 < n)     out[p0 * 3 + col]       = c[0];
                if (p0 + 8 < n) out[(p0 + 8) * 3 + col] = c[2];
            }
            if (col + 1 < 3) {
                if (p0 < n)     out[p0 * 3 + col + 1]       = c[1];
                if (p0 + 8 < n) out[(p0 + 8) * 3 + col + 1] = c[3];
            }
        }

        ub = ubn; vb = vbn; idb = idbn;
        ug0 = ug0n; vg0 = vg0n; ug1 = ug1n; vg1 = vg1n;
    }
}

extern "C" void kernel_launch(void* const* d_in, const int* in_sizes, int n_in,
                              void* d_out, int out_size) {
    const float* x    = (const float*)d_in[0];
    const float4* e0  = (const float4*)d_in[1];
    const float4* e1  = (const float4*)d_in[2];
    const float4* e2  = (const float4*)d_in[3];
    const float* w1   = (const float*)d_in[4];
    const float* b1   = (const float*)d_in[5];
    const float* w2   = (const float*)d_in[6];
    const float* b2   = (const float*)d_in[7];
    const float* w3   = (const float*)d_in[8];
    const float* b3   = (const float*)d_in[9];
    float* out        = (float*)d_out;
    int n = in_sizes[0] / 3;
    (void)n_in; (void)out_size;
    cudaFuncSetAttribute(densegrid_kernel,
                         cudaFuncAttributeMaxDynamicSharedMemorySize, SMEM_BYTES);
    densegrid_kernel<<<NCTA, THREADS, SMEM_BYTES>>>(
        x, e0, e1, e2, w1, b1, w2, b2, w3, b3, out, n);
}